// round 1
// baseline (speedup 1.0000x reference)
#include <cuda_runtime.h>
#include <cuda_bf16.h>
#include <math.h>

#define NB  4
#define NT  256
#define NV  1024
#define NS  64
#define ND  1024
#define NCV 256
#define NBT (NB*NT)

// ---------------- scratch (device globals; no allocs allowed) ----------------
__device__ float g_P[2][NCV*ND];   // P1 = Wu@Wk, P2 = Wu@Wv   (256 x 1024 each)
__device__ float g_rvec[ND];       // bu @ Wk
__device__ float g_bo[ND];         // bu @ Wv
__device__ float g_Z[NBT*NCV];     // per-token query folded to CV space
__device__ int   g_idx[NBT*NS];
__device__ int   g_cnt[NBT];
__device__ float g_qk[NBT*NS];
__device__ float g_m[NBT], g_l[NBT];
__device__ float g_mb[NB], g_lb[NB];   // batch max, 1/sumexp
__device__ float g_G[NBT*NCV];
__device__ float g_w[NBT];
__device__ int   g_flags;          // mask-format detection flags (idempotent)

// ---------------- mask format detection ----------------
// flags: 1 = word>1 seen (not pure 0/1 int32), 2 = 0x3F800000 seen (f32 1.0),
//        4 = 0x3F803F80 (bf16 pair), 8 = 0x00003F80 (bf16 low half)
__global__ void detect_mask_kernel(const unsigned* __restrict__ m, int nwords) {
    int f = 0;
    for (int i = blockIdx.x * blockDim.x + threadIdx.x; i < nwords;
         i += gridDim.x * blockDim.x) {
        unsigned w = m[i];
        if (w > 1u)              f |= 1;
        if (w == 0x3F800000u)    f |= 2;
        if (w == 0x3F803F80u)    f |= 4;
        if (w == 0x00003F80u)    f |= 8;
    }
    if (f) atomicOr(&g_flags, f);
}

// ---------------- index extraction: one warp per (b,t) ----------------
__global__ void extract_idx_kernel(const void* __restrict__ mraw) {
    int bt = blockIdx.x;
    int b = bt / NT, t = bt % NT;
    int lane = threadIdx.x;
    int flags = g_flags;
    // 0=int32, 1=uint8, 2=float32, 3=bf16
    int fmt = (flags & (4 | 8)) ? 3 : (flags & 2) ? 2 : (flags & 1) ? 1 : 0;
    int cnt = 0;
    const size_t base = (size_t)b * NV * NT + t;   // element index; stride NT over v
    for (int c = 0; c < NV / 32; c++) {
        int v = c * 32 + lane;
        size_t e = base + (size_t)v * NT;
        bool on;
        if (fmt == 0)      on = ((const int*)mraw)[e] != 0;
        else if (fmt == 1) on = ((const unsigned char*)mraw)[e] != 0;
        else if (fmt == 2) on = ((const float*)mraw)[e] != 0.0f;
        else               on = ((const unsigned short*)mraw)[e] != 0;
        unsigned bal = __ballot_sync(0xFFFFFFFFu, on);
        if (on) {
            int pos = cnt + __popc(bal & ((1u << lane) - 1u));
            if (pos < NS) g_idx[bt * NS + pos] = v;
        }
        cnt += __popc(bal);
    }
    if (cnt > NS) cnt = NS;
    if (lane == 0) g_cnt[bt] = cnt;
    for (int s = cnt + lane; s < NS; s += 32) g_idx[bt * NS + s] = NV;   // pad
}

// ---------------- rvec = bu@Wk, bo = bu@Wv ----------------
// grid 32, block 256: block handles 64 outputs; 4 K-slices per output.
__global__ void rbo_kernel(const float* __restrict__ Wk,
                           const float* __restrict__ Wv,
                           const float* __restrict__ bu) {
    __shared__ float red[256];
    int blk = blockIdx.x;                 // 0..31  (0..15 -> rvec, 16..31 -> bo)
    const float* W = (blk < 16) ? Wk : Wv;
    int jbase = (blk & 15) * 64;
    int jl = threadIdx.x & 63;            // 0..63
    int isl = threadIdx.x >> 6;           // 0..3
    int j = jbase + jl;
    float s = 0.f;
    int i0 = isl * 256;
    #pragma unroll 8
    for (int i = 0; i < 256; i++) {
        int ii = i0 + i;
        s += bu[ii] * W[(size_t)ii * ND + j];
    }
    red[threadIdx.x] = s;
    __syncthreads();
    if (isl == 0) {
        float tot = red[jl] + red[64 + jl] + red[128 + jl] + red[192 + jl];
        if (blk < 16) g_rvec[j] = tot; else g_bo[j] = tot;
    }
}

// ---------------- generic fp32 tiled GEMM ----------------
// C[z] = A @ B[z]  (TRANSB: B is (N,K) row-major; else (K,N))
// EPI:  C = acc + wrow[r]*bocol[c] + Xadd[r*N+c]
template <bool TRANSB, bool EPI>
__global__ void gemm_kernel(const float* __restrict__ A,
                            const float* __restrict__ B0,
                            const float* __restrict__ B1,
                            float* __restrict__ C,
                            int M, int N, int K,
                            const float* __restrict__ wrow,
                            const float* __restrict__ bocol,
                            const float* __restrict__ Xadd) {
    const int BM = 64, BN = 64, BK = 16;
    __shared__ float As[BK][BM + 1];
    __shared__ float Bs[BK][BN + 1];
    const float* B = (blockIdx.z == 0) ? B0 : B1;
    float* Cz = C + (size_t)blockIdx.z * M * N;
    int row0 = blockIdx.y * BM, col0 = blockIdx.x * BN;
    int tid = threadIdx.x;
    int tx = tid & 15, ty = tid >> 4;
    float acc[4][4] = {};
    for (int k0 = 0; k0 < K; k0 += BK) {
        #pragma unroll
        for (int it = 0; it < 4; it++) {
            int e = it * 256 + tid;
            int m = e >> 4, k = e & 15;
            As[k][m] = A[(size_t)(row0 + m) * K + k0 + k];
        }
        #pragma unroll
        for (int it = 0; it < 4; it++) {
            int e = it * 256 + tid;
            if (TRANSB) {
                int n = e >> 4, k = e & 15;
                Bs[k][n] = B[(size_t)(col0 + n) * K + k0 + k];
            } else {
                int k = e >> 6, n = e & 63;
                Bs[k][n] = B[(size_t)(k0 + k) * N + col0 + n];
            }
        }
        __syncthreads();
        #pragma unroll
        for (int k = 0; k < BK; k++) {
            float a[4], b[4];
            #pragma unroll
            for (int i = 0; i < 4; i++) a[i] = As[k][ty * 4 + i];
            #pragma unroll
            for (int j = 0; j < 4; j++) b[j] = Bs[k][tx * 4 + j];
            #pragma unroll
            for (int i = 0; i < 4; i++)
                #pragma unroll
                for (int j = 0; j < 4; j++)
                    acc[i][j] = fmaf(a[i], b[j], acc[i][j]);
        }
        __syncthreads();
    }
    #pragma unroll
    for (int i = 0; i < 4; i++) {
        int r = row0 + ty * 4 + i;
        #pragma unroll
        for (int j = 0; j < 4; j++) {
            int cc = col0 + tx * 4 + j;
            float v = acc[i][j];
            if (EPI) v += wrow[r] * bocol[cc] + Xadd[(size_t)r * N + cc];
            Cz[(size_t)r * N + cc] = v;
        }
    }
}

// ---------------- qk: gather-dot + per-(b,t) softmax stats ----------------
// block = 256 threads per (b,t)
__global__ void qk_kernel(const float* __restrict__ x,
                          const float* __restrict__ vision) {
    int bt = blockIdx.x, b = bt / NT;
    __shared__ float zs[NCV];
    __shared__ float red[256];
    __shared__ float qks[NS];
    int tid = threadIdx.x;
    zs[tid] = g_Z[bt * NCV + tid];
    // c0 = rvec . x_row
    const float* xr = x + (size_t)bt * ND;
    float p = 0.f;
    #pragma unroll
    for (int i = tid; i < ND; i += 256) p += g_rvec[i] * xr[i];
    red[tid] = p;
    __syncthreads();
    for (int o = 128; o > 0; o >>= 1) {
        if (tid < o) red[tid] += red[tid + o];
        __syncthreads();
    }
    float c0 = red[0];

    int w = tid >> 5, lane = tid & 31;
    const float* vb = vision + (size_t)b * NV * NCV;
    #pragma unroll
    for (int q = 0; q < 8; q++) {
        int s = w * 8 + q;
        int vidx = g_idx[bt * NS + s];
        float d = 0.f;
        if (vidx < NV) {
            const float* vr = vb + (size_t)vidx * NCV;
            #pragma unroll
            for (int i = 0; i < 8; i++) d += vr[lane + 32 * i] * zs[lane + 32 * i];
        }
        for (int o = 16; o > 0; o >>= 1) d += __shfl_down_sync(0xFFFFFFFFu, d, o);
        if (lane == 0) {
            float qk = (vidx < NV) ? (d + c0) * (1.f / 32.f) - 100.f
                                   : c0 * (1.f / 32.f);
            qks[s] = qk;
            g_qk[bt * NS + s] = qk;
        }
    }
    __syncthreads();
    if (w == 0) {
        float q1 = qks[lane], q2 = qks[lane + 32];
        float mx = fmaxf(q1, q2);
        for (int o = 16; o > 0; o >>= 1)
            mx = fmaxf(mx, __shfl_xor_sync(0xFFFFFFFFu, mx, o));
        float l = expf(q1 - mx) + expf(q2 - mx);
        for (int o = 16; o > 0; o >>= 1) l += __shfl_xor_sync(0xFFFFFFFFu, l, o);
        if (lane == 0) { g_m[bt] = mx; g_l[bt] = l; }
    }
}

// ---------------- batch-global softmax merge (grid NB, block 256) -----------
__global__ void batch_reduce_kernel() {
    int b = blockIdx.x, t = threadIdx.x;
    __shared__ float red[256];
    float m = g_m[b * NT + t];
    red[t] = m;
    __syncthreads();
    for (int o = 128; o > 0; o >>= 1) {
        if (t < o) red[t] = fmaxf(red[t], red[t + o]);
        __syncthreads();
    }
    float M = red[0];
    __syncthreads();
    float l = g_l[b * NT + t] * expf(m - M);
    red[t] = l;
    __syncthreads();
    for (int o = 128; o > 0; o >>= 1) {
        if (t < o) red[t] += red[t + o];
        __syncthreads();
    }
    if (t == 0) { g_mb[b] = M; g_lb[b] = 1.f / red[0]; }
}

// ---------------- G = sum_s p_s * vision[idx_s], w = sum_s p_s --------------
__global__ void gather_g_kernel(const float* __restrict__ vision) {
    int bt = blockIdx.x, b = bt / NT;
    __shared__ float ps[NS];
    int tid = threadIdx.x;
    float M = g_mb[b], invL = g_lb[b];
    if (tid < NS) ps[tid] = expf(g_qk[bt * NS + tid] - M) * invL;
    __syncthreads();
    if (tid == 0) {
        float s = 0.f;
        #pragma unroll
        for (int i = 0; i < NS; i++) s += ps[i];
        g_w[bt] = s;
    }
    float acc = 0.f;
    const float* vb = vision + (size_t)b * NV * NCV;
    const int* ids = &g_idx[bt * NS];
    #pragma unroll 4
    for (int s = 0; s < NS; s++) {
        int vi = ids[s];
        if (vi < NV) acc += ps[s] * vb[(size_t)vi * NCV + tid];
    }
    g_G[bt * NCV + tid] = acc;
}

// ---------------- launch ----------------
extern "C" void kernel_launch(void* const* d_in, const int* in_sizes, int n_in,
                              void* d_out, int out_size) {
    const float* x      = (const float*)d_in[0];
    const float* vision = (const float*)d_in[1];
    const void*  mask   = d_in[2];
    const float* Wu     = (const float*)d_in[3];
    const float* bu     = (const float*)d_in[4];
    const float* Wk     = (const float*)d_in[5];
    const float* Wv     = (const float*)d_in[6];
    float* out = (float*)d_out;

    float *P1, *P2, *Z, *G;
    cudaGetSymbolAddress((void**)&P1, g_P);
    P2 = P1 + NCV * ND;
    cudaGetSymbolAddress((void**)&Z, g_Z);
    cudaGetSymbolAddress((void**)&G, g_G);
    float *rvec, *bo, *w;
    cudaGetSymbolAddress((void**)&rvec, g_rvec);
    cudaGetSymbolAddress((void**)&bo, g_bo);
    cudaGetSymbolAddress((void**)&w, g_w);

    // 1) mask format detection (scan only 1MB = min buffer size across encodings)
    detect_mask_kernel<<<128, 256>>>((const unsigned*)mask, (NB * NV * NT) / 4);
    // 2) per-(b,t) selected-index lists
    extract_idx_kernel<<<NBT, 32>>>(mask);
    // 3) rvec = bu@Wk, bo = bu@Wv
    rbo_kernel<<<32, 256>>>(Wk, Wv, bu);
    // 4) P1 = Wu@Wk, P2 = Wu@Wv   (batched over z)
    gemm_kernel<false, false><<<dim3(ND / 64, NCV / 64, 2), 256>>>(
        Wu, Wk, Wv, P1, NCV, ND, ND, nullptr, nullptr, nullptr);
    // 5) Z = X @ P1^T    (1024 x 256)
    gemm_kernel<true, false><<<dim3(NCV / 64, NBT / 64, 1), 256>>>(
        x, P1, nullptr, Z, NBT, NCV, ND, nullptr, nullptr, nullptr);
    // 6) qk + per-token softmax stats
    qk_kernel<<<NBT, 256>>>(x, vision);
    // 7) batch-global softmax normalization
    batch_reduce_kernel<<<NB, 256>>>();
    // 8) weighted gather G, row weights w
    gather_g_kernel<<<NBT, 256>>>(vision);
    // 9) out = G @ P2 + w*bo + x
    gemm_kernel<false, true><<<dim3(ND / 64, NBT / 64, 1), 256>>>(
        G, P2, nullptr, out, NBT, ND, NCV, w, bo, x);
}

// round 2
// speedup vs baseline: 1.6030x; 1.6030x over previous
#include <cuda_runtime.h>
#include <cuda_bf16.h>
#include <math.h>

#define NB  4
#define NT  256
#define NV  1024
#define NS  64
#define ND  1024
#define NCV 256
#define NBT (NB*NT)

// ---------------- scratch (device globals; no allocs allowed) ----------------
__device__ float g_P[2][NCV*ND];   // P1 = Wu@Wk, P2 = Wu@Wv   (256 x 1024 each)
__device__ float g_rvec[ND];       // bu @ Wk
__device__ float g_bo[ND];         // bu @ Wv
__device__ float g_Z[NBT*NCV];     // per-token query folded to CV space
__device__ int   g_idx[NBT*NS];
__device__ float g_qk[NBT*NS];
__device__ float g_m[NBT], g_l[NBT];
__device__ float g_mb[NB], g_lb[NB];   // batch max, 1/sumexp
__device__ float g_G[NBT*NCV];
__device__ float g_w[NBT];
__device__ int   g_flags;          // mask-format detection flags (idempotent)

// ---------------- tf32 helpers ----------------
__device__ __forceinline__ float cvt_tf32(float x) {
    asm("cvt.rna.tf32.f32 %0, %1;" : "=f"(x) : "f"(x));
    return x;
}
__device__ __forceinline__ void mma_tf32(float* c,
        unsigned a0, unsigned a1, unsigned a2, unsigned a3,
        unsigned b0, unsigned b1) {
    asm volatile(
        "mma.sync.aligned.m16n8k8.row.col.f32.tf32.tf32.f32 "
        "{%0,%1,%2,%3}, {%4,%5,%6,%7}, {%8,%9}, {%0,%1,%2,%3};"
        : "+f"(c[0]), "+f"(c[1]), "+f"(c[2]), "+f"(c[3])
        : "r"(a0), "r"(a1), "r"(a2), "r"(a3), "r"(b0), "r"(b1));
}

// ---------------- mask format detection ----------------
__global__ void detect_mask_kernel(const unsigned* __restrict__ m, int nwords) {
    int f = 0;
    for (int i = blockIdx.x * blockDim.x + threadIdx.x; i < nwords;
         i += gridDim.x * blockDim.x) {
        unsigned w = m[i];
        if (w > 1u)              f |= 1;
        if (w == 0x3F800000u)    f |= 2;
        if (w == 0x3F803F80u)    f |= 4;
        if (w == 0x00003F80u)    f |= 8;
    }
    if (f) atomicOr(&g_flags, f);
}

// ---------------- index extraction: one warp per (b,t) ----------------
__global__ void extract_idx_kernel(const void* __restrict__ mraw) {
    int bt = blockIdx.x;
    int b = bt / NT, t = bt % NT;
    int lane = threadIdx.x;
    int flags = g_flags;
    int fmt = (flags & (4 | 8)) ? 3 : (flags & 2) ? 2 : (flags & 1) ? 1 : 0;
    int cnt = 0;
    const size_t base = (size_t)b * NV * NT + t;
    for (int c = 0; c < NV / 32; c++) {
        int v = c * 32 + lane;
        size_t e = base + (size_t)v * NT;
        bool on;
        if (fmt == 0)      on = ((const int*)mraw)[e] != 0;
        else if (fmt == 1) on = ((const unsigned char*)mraw)[e] != 0;
        else if (fmt == 2) on = ((const float*)mraw)[e] != 0.0f;
        else               on = ((const unsigned short*)mraw)[e] != 0;
        unsigned bal = __ballot_sync(0xFFFFFFFFu, on);
        if (on) {
            int pos = cnt + __popc(bal & ((1u << lane) - 1u));
            if (pos < NS) g_idx[bt * NS + pos] = v;
        }
        cnt += __popc(bal);
    }
    if (cnt > NS) cnt = NS;
    for (int s = cnt + lane; s < NS; s += 32) g_idx[bt * NS + s] = NV;   // pad
}

// ---------------- rvec = bu@Wk, bo = bu@Wv ----------------
__global__ void rbo_kernel(const float* __restrict__ Wk,
                           const float* __restrict__ Wv,
                           const float* __restrict__ bu) {
    __shared__ float red[256];
    int blk = blockIdx.x;                 // 0..31
    const float* W = (blk < 16) ? Wk : Wv;
    int jbase = (blk & 15) * 64;
    int jl = threadIdx.x & 63;
    int isl = threadIdx.x >> 6;
    int j = jbase + jl;
    float s = 0.f;
    int i0 = isl * 256;
    #pragma unroll 8
    for (int i = 0; i < 256; i++) {
        int ii = i0 + i;
        s += bu[ii] * W[(size_t)ii * ND + j];
    }
    red[threadIdx.x] = s;
    __syncthreads();
    if (isl == 0) {
        float tot = red[jl] + red[64 + jl] + red[128 + jl] + red[192 + jl];
        if (blk < 16) g_rvec[j] = tot; else g_bo[j] = tot;
    }
}

// ---------------- tf32 tensor-core GEMM ----------------
// C[z] = A @ B[z]  (TRANSB: B is (N,K) row-major; else (K,N))
// EPI:  C = acc + wrow[r]*bocol[c] + Xadd[r*N+c]
// block tile 64x64, BK=32, 128 threads = 4 warps (2x2), warp tile 32x32
template <bool TRANSB, bool EPI>
__global__ __launch_bounds__(128) void mma_gemm_kernel(
        const float* __restrict__ A,
        const float* __restrict__ B0,
        const float* __restrict__ B1,
        float* __restrict__ C,
        int M, int N, int K,
        const float* __restrict__ wrow,
        const float* __restrict__ bocol,
        const float* __restrict__ Xadd) {
    constexpr int BM = 64, BN = 64, BK = 32;
    __shared__ float As[BM][BK + 4];
    __shared__ float Bs[BK][BN + 4];
    const float* B = (blockIdx.z == 0) ? B0 : B1;
    float* Cz = C + (size_t)blockIdx.z * M * N;
    int row0 = blockIdx.y * BM, col0 = blockIdx.x * BN;
    int tid = threadIdx.x;
    int warp = tid >> 5, lane = tid & 31;
    int wm = warp >> 1, wn = warp & 1;
    int g = lane >> 2, tg = lane & 3;
    float acc[2][4][4] = {};

    for (int k0 = 0; k0 < K; k0 += BK) {
        // stage A: 64x32 floats, float4 along K, convert to tf32 at store
        #pragma unroll
        for (int it = 0; it < 4; it++) {
            int e = it * 128 + tid;            // 0..511 float4 slots
            int m = e >> 3, kq = e & 7;
            float4 v = *(const float4*)&A[(size_t)(row0 + m) * K + k0 + kq * 4];
            int kk = kq * 4;
            As[m][kk]     = cvt_tf32(v.x);
            As[m][kk + 1] = cvt_tf32(v.y);
            As[m][kk + 2] = cvt_tf32(v.z);
            As[m][kk + 3] = cvt_tf32(v.w);
        }
        // stage B
        #pragma unroll
        for (int it = 0; it < 4; it++) {
            int e = it * 128 + tid;
            if (TRANSB) {
                int n = e >> 3, kq = e & 7;    // read along K of B[n]
                float4 v = *(const float4*)&B[(size_t)(col0 + n) * K + k0 + kq * 4];
                int kk = kq * 4;
                Bs[kk][n]     = cvt_tf32(v.x);
                Bs[kk + 1][n] = cvt_tf32(v.y);
                Bs[kk + 2][n] = cvt_tf32(v.z);
                Bs[kk + 3][n] = cvt_tf32(v.w);
            } else {
                int k = e >> 4, nq = e & 15;   // read along N
                float4 v = *(const float4*)&B[(size_t)(k0 + k) * N + col0 + nq * 4];
                int nn = nq * 4;
                Bs[k][nn]     = cvt_tf32(v.x);
                Bs[k][nn + 1] = cvt_tf32(v.y);
                Bs[k][nn + 2] = cvt_tf32(v.z);
                Bs[k][nn + 3] = cvt_tf32(v.w);
            }
        }
        __syncthreads();

        #pragma unroll
        for (int ks = 0; ks < BK; ks += 8) {
            unsigned bf[4][2];
            #pragma unroll
            for (int ni = 0; ni < 4; ni++) {
                int col = wn * 32 + ni * 8 + g;
                bf[ni][0] = __float_as_uint(Bs[ks + tg][col]);
                bf[ni][1] = __float_as_uint(Bs[ks + tg + 4][col]);
            }
            #pragma unroll
            for (int mi = 0; mi < 2; mi++) {
                int r = wm * 32 + mi * 16;
                unsigned a0 = __float_as_uint(As[r + g][ks + tg]);
                unsigned a1 = __float_as_uint(As[r + 8 + g][ks + tg]);
                unsigned a2 = __float_as_uint(As[r + g][ks + tg + 4]);
                unsigned a3 = __float_as_uint(As[r + 8 + g][ks + tg + 4]);
                #pragma unroll
                for (int ni = 0; ni < 4; ni++)
                    mma_tf32(acc[mi][ni], a0, a1, a2, a3, bf[ni][0], bf[ni][1]);
            }
        }
        __syncthreads();
    }

    // epilogue
    #pragma unroll
    for (int mi = 0; mi < 2; mi++) {
        #pragma unroll
        for (int ni = 0; ni < 4; ni++) {
            int r = row0 + wm * 32 + mi * 16 + g;
            int c = col0 + wn * 32 + ni * 8 + tg * 2;
            float* a4 = acc[mi][ni];
            #pragma unroll
            for (int h = 0; h < 2; h++) {       // rows r, r+8
                int rr = r + h * 8;
                float v0 = a4[h * 2], v1 = a4[h * 2 + 1];
                if (EPI) {
                    float wr = wrow[rr];
                    v0 += wr * bocol[c]     + Xadd[(size_t)rr * N + c];
                    v1 += wr * bocol[c + 1] + Xadd[(size_t)rr * N + c + 1];
                }
                Cz[(size_t)rr * N + c]     = v0;
                Cz[(size_t)rr * N + c + 1] = v1;
            }
        }
    }
}

// ---------------- qk: gather-dot + per-(b,t) softmax stats ----------------
__global__ void qk_kernel(const float* __restrict__ x,
                          const float* __restrict__ vision) {
    int bt = blockIdx.x, b = bt / NT;
    __shared__ float zs[NCV];
    __shared__ float red[256];
    __shared__ float qks[NS];
    int tid = threadIdx.x;
    zs[tid] = g_Z[bt * NCV + tid];
    const float* xr = x + (size_t)bt * ND;
    float p = 0.f;
    #pragma unroll
    for (int i = tid; i < ND; i += 256) p += g_rvec[i] * xr[i];
    red[tid] = p;
    __syncthreads();
    for (int o = 128; o > 0; o >>= 1) {
        if (tid < o) red[tid] += red[tid + o];
        __syncthreads();
    }
    float c0 = red[0];

    int w = tid >> 5, lane = tid & 31;
    const float* vb = vision + (size_t)b * NV * NCV;
    #pragma unroll
    for (int q = 0; q < 8; q++) {
        int s = w * 8 + q;
        int vidx = g_idx[bt * NS + s];
        float d = 0.f;
        if (vidx < NV) {
            const float* vr = vb + (size_t)vidx * NCV;
            #pragma unroll
            for (int i = 0; i < 8; i++) d += vr[lane + 32 * i] * zs[lane + 32 * i];
        }
        for (int o = 16; o > 0; o >>= 1) d += __shfl_down_sync(0xFFFFFFFFu, d, o);
        if (lane == 0) {
            float qk = (vidx < NV) ? (d + c0) * (1.f / 32.f) - 100.f
                                   : c0 * (1.f / 32.f);
            qks[s] = qk;
            g_qk[bt * NS + s] = qk;
        }
    }
    __syncthreads();
    if (w == 0) {
        float q1 = qks[lane], q2 = qks[lane + 32];
        float mx = fmaxf(q1, q2);
        for (int o = 16; o > 0; o >>= 1)
            mx = fmaxf(mx, __shfl_xor_sync(0xFFFFFFFFu, mx, o));
        float l = expf(q1 - mx) + expf(q2 - mx);
        for (int o = 16; o > 0; o >>= 1) l += __shfl_xor_sync(0xFFFFFFFFu, l, o);
        if (lane == 0) { g_m[bt] = mx; g_l[bt] = l; }
    }
}

// ---------------- batch-global softmax merge ----------------
__global__ void batch_reduce_kernel() {
    int b = blockIdx.x, t = threadIdx.x;
    __shared__ float red[256];
    float m = g_m[b * NT + t];
    red[t] = m;
    __syncthreads();
    for (int o = 128; o > 0; o >>= 1) {
        if (t < o) red[t] = fmaxf(red[t], red[t + o]);
        __syncthreads();
    }
    float M = red[0];
    __syncthreads();
    float l = g_l[b * NT + t] * expf(m - M);
    red[t] = l;
    __syncthreads();
    for (int o = 128; o > 0; o >>= 1) {
        if (t < o) red[t] += red[t + o];
        __syncthreads();
    }
    if (t == 0) { g_mb[b] = M; g_lb[b] = 1.f / red[0]; }
}

// ---------------- G = sum_s p_s * vision[idx_s], w = sum_s p_s --------------
__global__ void gather_g_kernel(const float* __restrict__ vision) {
    int bt = blockIdx.x, b = bt / NT;
    __shared__ float ps[NS];
    int tid = threadIdx.x;
    float M = g_mb[b], invL = g_lb[b];
    if (tid < NS) ps[tid] = expf(g_qk[bt * NS + tid] - M) * invL;
    __syncthreads();
    if (tid == 0) {
        float s = 0.f;
        #pragma unroll
        for (int i = 0; i < NS; i++) s += ps[i];
        g_w[bt] = s;
    }
    float acc = 0.f;
    const float* vb = vision + (size_t)b * NV * NCV;
    const int* ids = &g_idx[bt * NS];
    #pragma unroll 4
    for (int s = 0; s < NS; s++) {
        int vi = ids[s];
        if (vi < NV) acc += ps[s] * vb[(size_t)vi * NCV + tid];
    }
    g_G[bt * NCV + tid] = acc;
}

// ---------------- launch ----------------
extern "C" void kernel_launch(void* const* d_in, const int* in_sizes, int n_in,
                              void* d_out, int out_size) {
    const float* x      = (const float*)d_in[0];
    const float* vision = (const float*)d_in[1];
    const void*  mask   = d_in[2];
    const float* Wu     = (const float*)d_in[3];
    const float* bu     = (const float*)d_in[4];
    const float* Wk     = (const float*)d_in[5];
    const float* Wv     = (const float*)d_in[6];
    float* out = (float*)d_out;

    float *P1, *P2, *Z, *G;
    cudaGetSymbolAddress((void**)&P1, g_P);
    P2 = P1 + NCV * ND;
    cudaGetSymbolAddress((void**)&Z, g_Z);
    cudaGetSymbolAddress((void**)&G, g_G);
    float *rvec, *bo, *w;
    cudaGetSymbolAddress((void**)&rvec, g_rvec);
    cudaGetSymbolAddress((void**)&bo, g_bo);
    cudaGetSymbolAddress((void**)&w, g_w);

    // 1) mask format detection
    detect_mask_kernel<<<128, 256>>>((const unsigned*)mask, (NB * NV * NT) / 4);
    // 2) per-(b,t) selected-index lists
    extract_idx_kernel<<<NBT, 32>>>(mask);
    // 3) rvec = bu@Wk, bo = bu@Wv
    rbo_kernel<<<32, 256>>>(Wk, Wv, bu);
    // 4) P1 = Wu@Wk, P2 = Wu@Wv  (batched over z)  -- tf32 tensor cores
    mma_gemm_kernel<false, false><<<dim3(ND / 64, NCV / 64, 2), 128>>>(
        Wu, Wk, Wv, P1, NCV, ND, ND, nullptr, nullptr, nullptr);
    // 5) Z = X @ P1^T
    mma_gemm_kernel<true, false><<<dim3(NCV / 64, NBT / 64, 1), 128>>>(
        x, P1, nullptr, Z, NBT, NCV, ND, nullptr, nullptr, nullptr);
    // 6) qk + per-token softmax stats
    qk_kernel<<<NBT, 256>>>(x, vision);
    // 7) batch-global softmax normalization
    batch_reduce_kernel<<<NB, 256>>>();
    // 8) weighted gather G, row weights w
    gather_g_kernel<<<NBT, 256>>>(vision);
    // 9) out = G @ P2 + w*bo + x
    mma_gemm_kernel<false, true><<<dim3(ND / 64, NBT / 64, 1), 128>>>(
        G, P2, nullptr, out, NBT, ND, NCV, w, bo, x);
}

// round 4
// speedup vs baseline: 2.2228x; 1.3867x over previous
#include <cuda_runtime.h>
#include <cuda_bf16.h>
#include <math.h>

#define NB  4
#define NT  256
#define NV  1024
#define NS  64
#define ND  1024
#define NCV 256
#define NBT (NB*NT)

// ---------------- scratch (device globals; no allocs allowed) ----------------
__device__ float g_P[2][NCV*ND];   // P1 = Wu@Wk, P2 = Wu@Wv
__device__ float g_rvec[ND];       // bu @ Wk
__device__ float g_bo[ND];         // bu @ Wv
__device__ float g_Z[NBT*NCV];
__device__ int   g_idx[NBT*NS];
__device__ float g_qk[NBT*NS];
__device__ float g_m[NBT], g_l[NBT];
__device__ float g_mb[NB], g_lb[NB];
__device__ float g_G[NBT*NCV];
__device__ float g_w[NBT];
__device__ int   g_flags;

// ---------------- helpers ----------------
__device__ __forceinline__ void mma_tf32(float* c,
        unsigned a0, unsigned a1, unsigned a2, unsigned a3,
        unsigned b0, unsigned b1) {
    asm volatile(
        "mma.sync.aligned.m16n8k8.row.col.f32.tf32.tf32.f32 "
        "{%0,%1,%2,%3}, {%4,%5,%6,%7}, {%8,%9}, {%0,%1,%2,%3};"
        : "+f"(c[0]), "+f"(c[1]), "+f"(c[2]), "+f"(c[3])
        : "r"(a0), "r"(a1), "r"(a2), "r"(a3), "r"(b0), "r"(b1));
}
__device__ __forceinline__ void cp16(float* smem, const float* g) {
    unsigned s = (unsigned)__cvta_generic_to_shared(smem);
    asm volatile("cp.async.cg.shared.global [%0], [%1], 16;\n" :: "r"(s), "l"(g));
}
__device__ __forceinline__ void cp_commit() {
    asm volatile("cp.async.commit_group;\n");
}
__device__ __forceinline__ void cp_wait_all() {
    asm volatile("cp.async.wait_group 0;\n");
}

// ---------------- mask format detection ----------------
__global__ void detect_mask_kernel(const unsigned* __restrict__ m, int nwords) {
    int f = 0;
    for (int i = blockIdx.x * blockDim.x + threadIdx.x; i < nwords;
         i += gridDim.x * blockDim.x) {
        unsigned w = m[i];
        if (w > 1u)              f |= 1;
        if (w == 0x3F800000u)    f |= 2;
        if (w == 0x3F803F80u)    f |= 4;
        if (w == 0x00003F80u)    f |= 8;
    }
    if (f) atomicOr(&g_flags, f);
}

// ---------------- index extraction: one warp per (b,t) ----------------
__global__ void extract_idx_kernel(const void* __restrict__ mraw) {
    int bt = blockIdx.x;
    int b = bt / NT, t = bt % NT;
    int lane = threadIdx.x;
    int flags = g_flags;
    int fmt = (flags & (4 | 8)) ? 3 : (flags & 2) ? 2 : (flags & 1) ? 1 : 0;
    int cnt = 0;
    const size_t base = (size_t)b * NV * NT + t;
    for (int c = 0; c < NV / 32; c++) {
        int v = c * 32 + lane;
        size_t e = base + (size_t)v * NT;
        bool on;
        if (fmt == 0)      on = ((const int*)mraw)[e] != 0;
        else if (fmt == 1) on = ((const unsigned char*)mraw)[e] != 0;
        else if (fmt == 2) on = ((const float*)mraw)[e] != 0.0f;
        else               on = ((const unsigned short*)mraw)[e] != 0;
        unsigned bal = __ballot_sync(0xFFFFFFFFu, on);
        if (on) {
            int pos = cnt + __popc(bal & ((1u << lane) - 1u));
            if (pos < NS) g_idx[bt * NS + pos] = v;
        }
        cnt += __popc(bal);
    }
    if (cnt > NS) cnt = NS;
    for (int s = cnt + lane; s < NS; s += 32) g_idx[bt * NS + s] = NV;
}

// ---------------- rvec = bu@Wk, bo = bu@Wv ----------------
__global__ void rbo_kernel(const float* __restrict__ Wk,
                           const float* __restrict__ Wv,
                           const float* __restrict__ bu) {
    __shared__ float red[256];
    int blk = blockIdx.x;
    const float* W = (blk < 16) ? Wk : Wv;
    int jbase = (blk & 15) * 64;
    int jl = threadIdx.x & 63;
    int isl = threadIdx.x >> 6;
    int j = jbase + jl;
    float s = 0.f;
    int i0 = isl * 256;
    #pragma unroll 8
    for (int i = 0; i < 256; i++) {
        int ii = i0 + i;
        s += bu[ii] * W[(size_t)ii * ND + j];
    }
    red[threadIdx.x] = s;
    __syncthreads();
    if (isl == 0) {
        float tot = red[jl] + red[64 + jl] + red[128 + jl] + red[192 + jl];
        if (blk < 16) g_rvec[j] = tot; else g_bo[j] = tot;
    }
}

// ---------------- pipelined tf32 tensor-core GEMM ----------------
// C[z] = A @ B[z]  (TRANSB: B is (N,K) row-major; else (K,N))
// EPI:  C = acc + wrow[r]*bocol[c] + Xadd[r*N+c]
// 64x64 block tile, BK=32, 256 threads (8 warps, 2x4), cp.async double buffer.
template <bool TRANSB, bool EPI>
__global__ __launch_bounds__(256) void mma_gemm_kernel(
        const float* __restrict__ A,
        const float* __restrict__ B0,
        const float* __restrict__ B1,
        float* __restrict__ C,
        int M, int N, int K,
        const float* __restrict__ wrow,
        const float* __restrict__ bocol,
        const float* __restrict__ Xadd) {
    constexpr int BK = 32;
    constexpr int ASTR = 36;   // A / B-trans smem row stride (floats)
    constexpr int BSTR = 72;   // B-notrans smem row stride
    constexpr int TSZ = 2304;  // 64*36 == 32*72
    __shared__ float smA[2][TSZ];
    __shared__ float smB[2][TSZ];

    const float* B = (blockIdx.z == 0) ? B0 : B1;
    float* Cz = C + (size_t)blockIdx.z * M * N;
    int row0 = blockIdx.y * 64, col0 = blockIdx.x * 64;
    int tid = threadIdx.x;
    int warp = tid >> 5, lane = tid & 31;
    int wm = warp >> 2, wn = warp & 3;       // 2 x 4 warp grid
    int g = lane >> 2, tg = lane & 3;

    float acc[2][2][4] = {};

    auto load_stage = [&](int s, int k0) {
        #pragma unroll
        for (int it = 0; it < 2; it++) {
            int e = it * 256 + tid;          // 512 float4 slots
            int m = e >> 3, kq = e & 7;
            cp16(&smA[s][m * ASTR + kq * 4],
                 &A[(size_t)(row0 + m) * K + k0 + kq * 4]);
        }
        #pragma unroll
        for (int it = 0; it < 2; it++) {
            int e = it * 256 + tid;
            if (TRANSB) {
                int n = e >> 3, kq = e & 7;
                cp16(&smB[s][n * ASTR + kq * 4],
                     &B[(size_t)(col0 + n) * K + k0 + kq * 4]);
            } else {
                int k = e >> 4, nq = e & 15;
                cp16(&smB[s][k * BSTR + nq * 4],
                     &B[(size_t)(k0 + k) * N + col0 + nq * 4]);
            }
        }
        cp_commit();
    };

    int niter = K / BK;
    load_stage(0, 0);

    for (int it = 0; it < niter; it++) {
        cp_wait_all();
        __syncthreads();
        if (it + 1 < niter) load_stage((it + 1) & 1, (it + 1) * BK);

        const float* As_ = smA[it & 1];
        const float* Bs_ = smB[it & 1];
        #pragma unroll
        for (int ks = 0; ks < BK; ks += 8) {
            unsigned a[2][4];
            #pragma unroll
            for (int mi = 0; mi < 2; mi++) {
                int r = wm * 32 + mi * 16;
                a[mi][0] = __float_as_uint(As_[(r + g) * ASTR + ks + tg]);
                a[mi][1] = __float_as_uint(As_[(r + 8 + g) * ASTR + ks + tg]);
                a[mi][2] = __float_as_uint(As_[(r + g) * ASTR + ks + tg + 4]);
                a[mi][3] = __float_as_uint(As_[(r + 8 + g) * ASTR + ks + tg + 4]);
            }
            unsigned b[2][2];
            #pragma unroll
            for (int ni = 0; ni < 2; ni++) {
                int c = wn * 16 + ni * 8 + g;
                if (TRANSB) {
                    b[ni][0] = __float_as_uint(Bs_[c * ASTR + ks + tg]);
                    b[ni][1] = __float_as_uint(Bs_[c * ASTR + ks + tg + 4]);
                } else {
                    b[ni][0] = __float_as_uint(Bs_[(ks + tg) * BSTR + c]);
                    b[ni][1] = __float_as_uint(Bs_[(ks + tg + 4) * BSTR + c]);
                }
            }
            #pragma unroll
            for (int mi = 0; mi < 2; mi++)
                #pragma unroll
                for (int ni = 0; ni < 2; ni++)
                    mma_tf32(acc[mi][ni], a[mi][0], a[mi][1], a[mi][2], a[mi][3],
                             b[ni][0], b[ni][1]);
        }
        __syncthreads();
    }

    // epilogue
    #pragma unroll
    for (int mi = 0; mi < 2; mi++) {
        #pragma unroll
        for (int ni = 0; ni < 2; ni++) {
            int r = row0 + wm * 32 + mi * 16 + g;
            int c = col0 + wn * 16 + ni * 8 + tg * 2;
            float* a4 = acc[mi][ni];
            #pragma unroll
            for (int h = 0; h < 2; h++) {
                int rr = r + h * 8;
                float v0 = a4[h * 2], v1 = a4[h * 2 + 1];
                if (EPI) {
                    float wr = wrow[rr];
                    v0 += wr * bocol[c]     + Xadd[(size_t)rr * N + c];
                    v1 += wr * bocol[c + 1] + Xadd[(size_t)rr * N + c + 1];
                }
                Cz[(size_t)rr * N + c]     = v0;
                Cz[(size_t)rr * N + c + 1] = v1;
            }
        }
    }
}

// ---------------- qk: gather-dot + per-(b,t) softmax stats ----------------
__global__ void qk_kernel(const float* __restrict__ x,
                          const float* __restrict__ vision) {
    int bt = blockIdx.x, b = bt / NT;
    __shared__ float zs[NCV];
    __shared__ float red[256];
    __shared__ float qks[NS];
    int tid = threadIdx.x;
    zs[tid] = g_Z[bt * NCV + tid];
    const float* xr = x + (size_t)bt * ND;
    float p = 0.f;
    #pragma unroll
    for (int i = tid; i < ND; i += 256) p += g_rvec[i] * xr[i];
    red[tid] = p;
    __syncthreads();
    for (int o = 128; o > 0; o >>= 1) {
        if (tid < o) red[tid] += red[tid + o];
        __syncthreads();
    }
    float c0 = red[0];

    int w = tid >> 5, lane = tid & 31;
    const float* vb = vision + (size_t)b * NV * NCV;
    #pragma unroll
    for (int q = 0; q < 8; q++) {
        int s = w * 8 + q;
        int vidx = g_idx[bt * NS + s];
        float d = 0.f;
        if (vidx < NV) {
            const float* vr = vb + (size_t)vidx * NCV;
            #pragma unroll
            for (int i = 0; i < 8; i++) d += vr[lane + 32 * i] * zs[lane + 32 * i];
        }
        for (int o = 16; o > 0; o >>= 1) d += __shfl_down_sync(0xFFFFFFFFu, d, o);
        if (lane == 0) {
            float qk = (vidx < NV) ? (d + c0) * (1.f / 32.f) - 100.f
                                   : c0 * (1.f / 32.f);
            qks[s] = qk;
            g_qk[bt * NS + s] = qk;
        }
    }
    __syncthreads();
    if (w == 0) {
        float q1 = qks[lane], q2 = qks[lane + 32];
        float mx = fmaxf(q1, q2);
        for (int o = 16; o > 0; o >>= 1)
            mx = fmaxf(mx, __shfl_xor_sync(0xFFFFFFFFu, mx, o));
        float l = expf(q1 - mx) + expf(q2 - mx);
        for (int o = 16; o > 0; o >>= 1) l += __shfl_xor_sync(0xFFFFFFFFu, l, o);
        if (lane == 0) { g_m[bt] = mx; g_l[bt] = l; }
    }
}

// ---------------- batch-global softmax merge ----------------
__global__ void batch_reduce_kernel() {
    int b = blockIdx.x, t = threadIdx.x;
    __shared__ float red[256];
    float m = g_m[b * NT + t];
    red[t] = m;
    __syncthreads();
    for (int o = 128; o > 0; o >>= 1) {
        if (t < o) red[t] = fmaxf(red[t], red[t + o]);
        __syncthreads();
    }
    float M = red[0];
    __syncthreads();
    float l = g_l[b * NT + t] * expf(m - M);
    red[t] = l;
    __syncthreads();
    for (int o = 128; o > 0; o >>= 1) {
        if (t < o) red[t] += red[t + o];
        __syncthreads();
    }
    if (t == 0) { g_mb[b] = M; g_lb[b] = 1.f / red[0]; }
}

// ---------------- G = sum_s p_s * vision[idx_s], w = sum_s p_s --------------
__global__ void gather_g_kernel(const float* __restrict__ vision) {
    int bt = blockIdx.x, b = bt / NT;
    __shared__ float ps[NS];
    int tid = threadIdx.x;
    float M = g_mb[b], invL = g_lb[b];
    if (tid < NS) ps[tid] = expf(g_qk[bt * NS + tid] - M) * invL;
    __syncthreads();
    if (tid == 0) {
        float s = 0.f;
        #pragma unroll
        for (int i = 0; i < NS; i++) s += ps[i];
        g_w[bt] = s;
    }
    float acc = 0.f;
    const float* vb = vision + (size_t)b * NV * NCV;
    const int* ids = &g_idx[bt * NS];
    #pragma unroll 4
    for (int s = 0; s < NS; s++) {
        int vi = ids[s];
        if (vi < NV) acc += ps[s] * vb[(size_t)vi * NCV + tid];
    }
    g_G[bt * NCV + tid] = acc;
}

// ---------------- launch ----------------
extern "C" void kernel_launch(void* const* d_in, const int* in_sizes, int n_in,
                              void* d_out, int out_size) {
    const float* x      = (const float*)d_in[0];
    const float* vision = (const float*)d_in[1];
    const void*  mask   = d_in[2];
    const float* Wu     = (const float*)d_in[3];
    const float* bu     = (const float*)d_in[4];
    const float* Wk     = (const float*)d_in[5];
    const float* Wv     = (const float*)d_in[6];
    float* out = (float*)d_out;

    float *P1, *P2, *Z, *G;
    cudaGetSymbolAddress((void**)&P1, g_P);
    P2 = P1 + NCV * ND;
    cudaGetSymbolAddress((void**)&Z, g_Z);
    cudaGetSymbolAddress((void**)&G, g_G);
    float *bo, *w;
    cudaGetSymbolAddress((void**)&bo, g_bo);
    cudaGetSymbolAddress((void**)&w, g_w);

    detect_mask_kernel<<<128, 256>>>((const unsigned*)mask, (NB * NV * NT) / 4);
    extract_idx_kernel<<<NBT, 32>>>(mask);
    rbo_kernel<<<32, 256>>>(Wk, Wv, bu);
    // P1 = Wu@Wk, P2 = Wu@Wv
    mma_gemm_kernel<false, false><<<dim3(ND / 64, NCV / 64, 2), 256>>>(
        Wu, Wk, Wv, P1, NCV, ND, ND, nullptr, nullptr, nullptr);
    // Z = X @ P1^T
    mma_gemm_kernel<true, false><<<dim3(NCV / 64, NBT / 64, 1), 256>>>(
        x, P1, nullptr, Z, NBT, NCV, ND, nullptr, nullptr, nullptr);
    qk_kernel<<<NBT, 256>>>(x, vision);
    batch_reduce_kernel<<<NB, 256>>>();
    gather_g_kernel<<<NBT, 256>>>(vision);
    // out = G @ P2 + w*bo + x
    mma_gemm_kernel<false, true><<<dim3(ND / 64, NBT / 64, 1), 256>>>(
        G, P2, nullptr, out, NBT, ND, NCV, w, bo, x);
}

// round 5
// speedup vs baseline: 2.5060x; 1.1274x over previous
#include <cuda_runtime.h>
#include <cuda_bf16.h>
#include <math.h>

#define NB  4
#define NT  256
#define NV  1024
#define NS  64
#define ND  1024
#define NCV 256
#define NBT (NB*NT)

// ---------------- scratch (device globals; no allocs allowed) ----------------
__device__ float g_Ph[4][NCV*ND];  // split-K halves: {P1h0,P1h1,P2h0,P2h1}
__device__ float g_P[2][NCV*ND];   // P1 = Wu@Wk, P2 = Wu@Wv
__device__ float g_rvec[ND];       // bu @ Wk
__device__ float g_bo[ND];         // bu @ Wv
__device__ float g_Zh[2][NBT*NCV]; // Z split-K halves (summed in qk staging)
__device__ int   g_idx[NBT*NS];
__device__ float g_qk[NBT*NS];
__device__ float g_m[NBT], g_l[NBT];
__device__ float g_G[NBT*NCV];
__device__ float g_w[NBT];
__device__ int   g_flags;

// ---------------- helpers ----------------
__device__ __forceinline__ void mma_tf32(float* c,
        unsigned a0, unsigned a1, unsigned a2, unsigned a3,
        unsigned b0, unsigned b1) {
    asm volatile(
        "mma.sync.aligned.m16n8k8.row.col.f32.tf32.tf32.f32 "
        "{%0,%1,%2,%3}, {%4,%5,%6,%7}, {%8,%9}, {%0,%1,%2,%3};"
        : "+f"(c[0]), "+f"(c[1]), "+f"(c[2]), "+f"(c[3])
        : "r"(a0), "r"(a1), "r"(a2), "r"(a3), "r"(b0), "r"(b1));
}
__device__ __forceinline__ void cp16(float* smem, const float* g) {
    unsigned s = (unsigned)__cvta_generic_to_shared(smem);
    asm volatile("cp.async.cg.shared.global [%0], [%1], 16;\n" :: "r"(s), "l"(g));
}
__device__ __forceinline__ void cp_commit() {
    asm volatile("cp.async.commit_group;\n");
}
__device__ __forceinline__ void cp_wait1() {
    asm volatile("cp.async.wait_group 1;\n");
}

// ---------------- mask format detection ----------------
__global__ void detect_mask_kernel(const unsigned* __restrict__ m, int nwords) {
    int f = 0;
    for (int i = blockIdx.x * blockDim.x + threadIdx.x; i < nwords;
         i += gridDim.x * blockDim.x) {
        unsigned w = m[i];
        if (w > 1u)              f |= 1;
        if (w == 0x3F800000u)    f |= 2;
        if (w == 0x3F803F80u)    f |= 4;
        if (w == 0x00003F80u)    f |= 8;
    }
    if (f) atomicOr(&g_flags, f);
}

// ---------------- index extraction: one warp per (b,t) ----------------
__global__ void extract_idx_kernel(const void* __restrict__ mraw) {
    int bt = blockIdx.x;
    int b = bt / NT, t = bt % NT;
    int lane = threadIdx.x;
    int flags = g_flags;
    int fmt = (flags & (4 | 8)) ? 3 : (flags & 2) ? 2 : (flags & 1) ? 1 : 0;
    int cnt = 0;
    const size_t base = (size_t)b * NV * NT + t;
    for (int c = 0; c < NV / 32; c++) {
        int v = c * 32 + lane;
        size_t e = base + (size_t)v * NT;
        bool on;
        if (fmt == 0)      on = ((const int*)mraw)[e] != 0;
        else if (fmt == 1) on = ((const unsigned char*)mraw)[e] != 0;
        else if (fmt == 2) on = ((const float*)mraw)[e] != 0.0f;
        else               on = ((const unsigned short*)mraw)[e] != 0;
        unsigned bal = __ballot_sync(0xFFFFFFFFu, on);
        if (on) {
            int pos = cnt + __popc(bal & ((1u << lane) - 1u));
            if (pos < NS) g_idx[bt * NS + pos] = v;
        }
        cnt += __popc(bal);
    }
    if (cnt > NS) cnt = NS;
    for (int s = cnt + lane; s < NS; s += 32) g_idx[bt * NS + s] = NV;
}

// ---------------- rvec = bu@Wk, bo = bu@Wv ----------------
__global__ void rbo_kernel(const float* __restrict__ Wk,
                           const float* __restrict__ Wv,
                           const float* __restrict__ bu) {
    __shared__ float red[256];
    int blk = blockIdx.x;
    const float* W = (blk < 16) ? Wk : Wv;
    int jbase = (blk & 15) * 64;
    int jl = threadIdx.x & 63;
    int isl = threadIdx.x >> 6;
    int j = jbase + jl;
    float s = 0.f;
    int i0 = isl * 256;
    #pragma unroll 8
    for (int i = 0; i < 256; i++) {
        int ii = i0 + i;
        s += bu[ii] * W[(size_t)ii * ND + j];
    }
    red[threadIdx.x] = s;
    __syncthreads();
    if (isl == 0) {
        float tot = red[jl] + red[64 + jl] + red[128 + jl] + red[192 + jl];
        if (blk < 16) g_rvec[j] = tot; else g_bo[j] = tot;
    }
}

// ---------------- 3-stage pipelined tf32 GEMM ----------------
// BM=64 fixed; BN in {32,64}; 256 threads = 8 warps (2 x 4), warp tile 32 x BN/4.
// MODE 0: z in 0..3 -> B = (z<2 ? B0 : B1), K-half = z&1, C = Cbase + z*csz
// MODE 1: TRANSB (B is N x K row-major); z = K-half; C = Cbase + z*csz
// MODE 2: plain, EPI: C = acc + wrow[r]*bocol[c] + Xadd[r*ldc+c]
template <int BN, int MODE>
__global__ __launch_bounds__(256) void gemm3_kernel(
        const float* __restrict__ A,
        const float* __restrict__ B0,
        const float* __restrict__ B1,
        float* __restrict__ C,
        int kiter, int lda, int ldb, int ldc, int csz,
        const float* __restrict__ wrow,
        const float* __restrict__ bocol,
        const float* __restrict__ Xadd) {
    constexpr bool TRANSB = (MODE == 1);
    constexpr int BM = 64, BK = 32;
    constexpr int ASTR = 36;
    constexpr int BSTR = TRANSB ? 36 : (BN + 8);
    constexpr int ATS = BM * ASTR;
    constexpr int BTS = TRANSB ? (BN * 36) : (BK * (BN + 8));
    constexpr int WN = BN / 4;
    constexpr int NI = WN / 8;
    constexpr int AITER = (BM * 8) / 256;
    constexpr int BITER = (8 * BN) / 256;
    __shared__ float smA[3][ATS];
    __shared__ float smB[3][BTS];

    const float* Ap = A;
    const float* Bp = B0;
    float* Cp = C;
    if (MODE == 0) {
        int zz = blockIdx.z;
        Bp = (zz < 2) ? B0 : B1;
        int kb = (zz & 1) * (kiter * BK);
        Ap = A + kb;
        Bp += (size_t)kb * ldb;
        Cp = C + (size_t)zz * csz;
    } else if (MODE == 1) {
        int zz = blockIdx.z;
        int kb = zz * (kiter * BK);
        Ap = A + kb;
        Bp = B0 + kb;           // TRANSB: column offset
        Cp = C + (size_t)zz * csz;
    }

    int row0 = blockIdx.y * BM, col0 = blockIdx.x * BN;
    int tid = threadIdx.x;
    int warp = tid >> 5, lane = tid & 31;
    int wm = warp >> 2, wn = warp & 3;
    int g = lane >> 2, tg = lane & 3;

    float acc[2][NI][4] = {};

    auto load_stage = [&](int s, int k0) {
        #pragma unroll
        for (int itr = 0; itr < AITER; itr++) {
            int e = itr * 256 + tid;
            int m = e >> 3, kq = e & 7;
            cp16(&smA[s][m * ASTR + kq * 4],
                 &Ap[(size_t)(row0 + m) * lda + k0 + kq * 4]);
        }
        #pragma unroll
        for (int itr = 0; itr < BITER; itr++) {
            int e = itr * 256 + tid;
            if (TRANSB) {
                int n = e >> 3, kq = e & 7;
                cp16(&smB[s][n * 36 + kq * 4],
                     &Bp[(size_t)(col0 + n) * ldb + k0 + kq * 4]);
            } else {
                int k = e / (BN / 4), nq = e % (BN / 4);
                cp16(&smB[s][k * BSTR + nq * 4],
                     &Bp[(size_t)(k0 + k) * ldb + col0 + nq * 4]);
            }
        }
        cp_commit();
    };

    load_stage(0, 0);
    load_stage(1, BK);

    for (int it = 0; it < kiter; it++) {
        cp_wait1();
        __syncthreads();
        if (it + 2 < kiter) load_stage((it + 2) % 3, (it + 2) * BK);
        else                cp_commit();          // keep group count stable

        const float* As_ = smA[it % 3];
        const float* Bs_ = smB[it % 3];
        #pragma unroll
        for (int ks = 0; ks < BK; ks += 8) {
            unsigned a[2][4];
            #pragma unroll
            for (int mi = 0; mi < 2; mi++) {
                int r = wm * 32 + mi * 16;
                a[mi][0] = __float_as_uint(As_[(r + g) * ASTR + ks + tg]);
                a[mi][1] = __float_as_uint(As_[(r + 8 + g) * ASTR + ks + tg]);
                a[mi][2] = __float_as_uint(As_[(r + g) * ASTR + ks + tg + 4]);
                a[mi][3] = __float_as_uint(As_[(r + 8 + g) * ASTR + ks + tg + 4]);
            }
            unsigned b[NI][2];
            #pragma unroll
            for (int ni = 0; ni < NI; ni++) {
                int c = wn * WN + ni * 8 + g;
                if (TRANSB) {
                    b[ni][0] = __float_as_uint(Bs_[c * 36 + ks + tg]);
                    b[ni][1] = __float_as_uint(Bs_[c * 36 + ks + tg + 4]);
                } else {
                    b[ni][0] = __float_as_uint(Bs_[(ks + tg) * BSTR + c]);
                    b[ni][1] = __float_as_uint(Bs_[(ks + tg + 4) * BSTR + c]);
                }
            }
            #pragma unroll
            for (int mi = 0; mi < 2; mi++)
                #pragma unroll
                for (int ni = 0; ni < NI; ni++)
                    mma_tf32(acc[mi][ni], a[mi][0], a[mi][1], a[mi][2], a[mi][3],
                             b[ni][0], b[ni][1]);
        }
        __syncthreads();
    }

    #pragma unroll
    for (int mi = 0; mi < 2; mi++) {
        #pragma unroll
        for (int ni = 0; ni < NI; ni++) {
            int r = row0 + wm * 32 + mi * 16 + g;
            int c = col0 + wn * WN + ni * 8 + tg * 2;
            float* a4 = acc[mi][ni];
            #pragma unroll
            for (int h = 0; h < 2; h++) {
                int rr = r + h * 8;
                float v0 = a4[h * 2], v1 = a4[h * 2 + 1];
                if (MODE == 2) {
                    float wr = wrow[rr];
                    v0 += wr * bocol[c]     + Xadd[(size_t)rr * ldc + c];
                    v1 += wr * bocol[c + 1] + Xadd[(size_t)rr * ldc + c + 1];
                }
                Cp[(size_t)rr * ldc + c]     = v0;
                Cp[(size_t)rr * ldc + c + 1] = v1;
            }
        }
    }
}

// ---------------- reduce split-K halves of P ----------------
__global__ void reduceP_kernel() {
    int z = blockIdx.y;
    int i = blockIdx.x * 256 + threadIdx.x;          // float4 index, 65536 per z
    const float4* h0 = (const float4*)g_Ph[2 * z];
    const float4* h1 = (const float4*)g_Ph[2 * z + 1];
    float4 a = h0[i], b = h1[i];
    float4 r = make_float4(a.x + b.x, a.y + b.y, a.z + b.z, a.w + b.w);
    ((float4*)g_P[z])[i] = r;
}

// ---------------- qk: gather-dot + per-(b,t) softmax stats ----------------
__global__ void qk_kernel(const float* __restrict__ x,
                          const float* __restrict__ vision) {
    int bt = blockIdx.x, b = bt / NT;
    __shared__ float zs[NCV];
    __shared__ float red[256];
    __shared__ float qks[NS];
    int tid = threadIdx.x;
    zs[tid] = g_Zh[0][bt * NCV + tid] + g_Zh[1][bt * NCV + tid];
    const float* xr = x + (size_t)bt * ND;
    float p = 0.f;
    #pragma unroll
    for (int i = tid; i < ND; i += 256) p += g_rvec[i] * xr[i];
    red[tid] = p;
    __syncthreads();
    for (int o = 128; o > 0; o >>= 1) {
        if (tid < o) red[tid] += red[tid + o];
        __syncthreads();
    }
    float c0 = red[0];

    int w = tid >> 5, lane = tid & 31;
    const float* vb = vision + (size_t)b * NV * NCV;
    #pragma unroll
    for (int q = 0; q < 8; q++) {
        int s = w * 8 + q;
        int vidx = g_idx[bt * NS + s];
        float d = 0.f;
        if (vidx < NV) {
            const float* vr = vb + (size_t)vidx * NCV;
            #pragma unroll
            for (int i = 0; i < 8; i++) d += vr[lane + 32 * i] * zs[lane + 32 * i];
        }
        for (int o = 16; o > 0; o >>= 1) d += __shfl_down_sync(0xFFFFFFFFu, d, o);
        if (lane == 0) {
            float qk = (vidx < NV) ? (d + c0) * (1.f / 32.f) - 100.f
                                   : c0 * (1.f / 32.f);
            qks[s] = qk;
            g_qk[bt * NS + s] = qk;
        }
    }
    __syncthreads();
    if (w == 0) {
        float q1 = qks[lane], q2 = qks[lane + 32];
        float mx = fmaxf(q1, q2);
        for (int o = 16; o > 0; o >>= 1)
            mx = fmaxf(mx, __shfl_xor_sync(0xFFFFFFFFu, mx, o));
        float l = expf(q1 - mx) + expf(q2 - mx);
        for (int o = 16; o > 0; o >>= 1) l += __shfl_xor_sync(0xFFFFFFFFu, l, o);
        if (lane == 0) { g_m[bt] = mx; g_l[bt] = l; }
    }
}

// ------- G = sum_s p_s * vision[idx_s], w = sum_s p_s (batch merge fused) ----
__global__ void gather_g_kernel(const float* __restrict__ vision) {
    int bt = blockIdx.x, b = bt / NT;
    __shared__ float ps[NS];
    __shared__ float red[256];
    int tid = threadIdx.x;

    // fused batch-global softmax merge (redundant per block; L2-hot)
    float m = g_m[b * NT + tid];
    red[tid] = m;
    __syncthreads();
    for (int o = 128; o > 0; o >>= 1) {
        if (tid < o) red[tid] = fmaxf(red[tid], red[tid + o]);
        __syncthreads();
    }
    float M = red[0];
    __syncthreads();
    red[tid] = g_l[b * NT + tid] * expf(m - M);
    __syncthreads();
    for (int o = 128; o > 0; o >>= 1) {
        if (tid < o) red[tid] += red[tid + o];
        __syncthreads();
    }
    float invL = 1.f / red[0];

    if (tid < NS) ps[tid] = expf(g_qk[bt * NS + tid] - M) * invL;
    __syncthreads();
    if (tid == 0) {
        float s = 0.f;
        #pragma unroll
        for (int i = 0; i < NS; i++) s += ps[i];
        g_w[bt] = s;
    }
    float acc = 0.f;
    const float* vb = vision + (size_t)b * NV * NCV;
    const int* ids = &g_idx[bt * NS];
    #pragma unroll 4
    for (int s = 0; s < NS; s++) {
        int vi = ids[s];
        if (vi < NV) acc += ps[s] * vb[(size_t)vi * NCV + tid];
    }
    g_G[bt * NCV + tid] = acc;
}

// ---------------- launch ----------------
extern "C" void kernel_launch(void* const* d_in, const int* in_sizes, int n_in,
                              void* d_out, int out_size) {
    const float* x      = (const float*)d_in[0];
    const float* vision = (const float*)d_in[1];
    const void*  mask   = d_in[2];
    const float* Wu     = (const float*)d_in[3];
    const float* bu     = (const float*)d_in[4];
    const float* Wk     = (const float*)d_in[5];
    const float* Wv     = (const float*)d_in[6];
    float* out = (float*)d_out;

    float *Ph, *P1, *P2, *Zh, *G;
    cudaGetSymbolAddress((void**)&Ph, g_Ph);
    cudaGetSymbolAddress((void**)&P1, g_P);
    P2 = P1 + NCV * ND;
    cudaGetSymbolAddress((void**)&Zh, g_Zh);
    cudaGetSymbolAddress((void**)&G, g_G);
    float *bo, *w;
    cudaGetSymbolAddress((void**)&bo, g_bo);
    cudaGetSymbolAddress((void**)&w, g_w);

    detect_mask_kernel<<<32, 256>>>((const unsigned*)mask, 32768);
    extract_idx_kernel<<<NBT, 32>>>(mask);
    rbo_kernel<<<32, 256>>>(Wk, Wv, bu);

    // P halves: grid (N/64, M/64, 4): z -> {P1,P2} x {K-half}; K=512 each
    gemm3_kernel<64, 0><<<dim3(ND / 64, NCV / 64, 4), 256>>>(
        Wu, Wk, Wv, Ph, 512 / 32, ND, ND, ND, NCV * ND, nullptr, nullptr, nullptr);
    reduceP_kernel<<<dim3(256, 2), 256>>>();

    // Z halves: Z = X @ P1^T, split-K=2, BN=32: grid (256/32, 1024/64, 2)
    gemm3_kernel<32, 1><<<dim3(NCV / 32, NBT / 64, 2), 256>>>(
        x, P1, nullptr, Zh, 512 / 32, ND, ND, NCV, NBT * NCV, nullptr, nullptr, nullptr);

    qk_kernel<<<NBT, 256>>>(x, vision);
    gather_g_kernel<<<NBT, 256>>>(vision);

    // out = G @ P2 + w*bo + x : grid (1024/64, 1024/64)
    gemm3_kernel<64, 2><<<dim3(ND / 64, NBT / 64, 1), 256>>>(
        G, P2, nullptr, out, NCV / 32, NCV, ND, ND, 0, w, bo, x);
}

// round 6
// speedup vs baseline: 2.9568x; 1.1799x over previous
#include <cuda_runtime.h>
#include <cuda_bf16.h>
#include <math.h>

#define NB  4
#define NT  256
#define NV  1024
#define NS  64
#define ND  1024
#define NCV 256
#define NBT (NB*NT)

// ---------------- scratch (device globals; no allocs allowed) ----------------
__device__ float          g_Ph[4][NCV*ND];   // split-K halves {P1h0,P1h1,P2h0,P2h1}
__device__ __nv_bfloat16  g_Wu16[NCV*ND];
__device__ __nv_bfloat16  g_WkT16[ND*ND];    // Wk^T  (n,k) k-contiguous
__device__ __nv_bfloat16  g_WvT16[ND*ND];    // Wv^T
__device__ __nv_bfloat16  g_x16[NBT*ND];
__device__ __nv_bfloat16  g_vis16[NB*NV*NCV];
__device__ __nv_bfloat16  g_P1_16[NCV*ND];   // P1 (n=256 rows, k=1024) k-contig
__device__ __nv_bfloat16  g_P2T16[ND*NCV];   // P2^T (n=1024 rows, k=256) k-contig
__device__ __nv_bfloat16  g_G16[NBT*NCV];
__device__ float g_rvec[ND];       // bu @ Wk
__device__ float g_bo[ND];         // bu @ Wv
__device__ float g_Zh[2][NBT*NCV]; // Z split-K halves (summed in qk staging)
__device__ int   g_idx[NBT*NS];
__device__ float g_qk[NBT*NS];
__device__ float g_m[NBT], g_l[NBT];
__device__ float g_w[NBT];
__device__ int   g_flags;

// ---------------- helpers ----------------
__device__ __forceinline__ void mma_bf16(float* c, const unsigned* a, const unsigned* b) {
    asm volatile(
        "mma.sync.aligned.m16n8k16.row.col.f32.bf16.bf16.f32 "
        "{%0,%1,%2,%3}, {%4,%5,%6,%7}, {%8,%9}, {%0,%1,%2,%3};"
        : "+f"(c[0]), "+f"(c[1]), "+f"(c[2]), "+f"(c[3])
        : "r"(a[0]), "r"(a[1]), "r"(a[2]), "r"(a[3]), "r"(b[0]), "r"(b[1]));
}
__device__ __forceinline__ void cp16(void* smem, const void* g) {
    unsigned s = (unsigned)__cvta_generic_to_shared(smem);
    asm volatile("cp.async.cg.shared.global [%0], [%1], 16;\n" :: "r"(s), "l"(g));
}
__device__ __forceinline__ void cp_commit() {
    asm volatile("cp.async.commit_group;\n");
}
__device__ __forceinline__ void cp_wait1() {
    asm volatile("cp.async.wait_group 1;\n");
}
__device__ __forceinline__ void st_bf16x4(__nv_bfloat16* p, float4 v) {
    __nv_bfloat162 lo = __floats2bfloat162_rn(v.x, v.y);
    __nv_bfloat162 hi = __floats2bfloat162_rn(v.z, v.w);
    uint2 u;
    u.x = *(unsigned*)&lo;
    u.y = *(unsigned*)&hi;
    *(uint2*)p = u;
}

// ---------------- fused prep: detect + rbo + convert + transpose-convert ----
// block ranges: [0,32) detect | [32,64) rbo | [64,320) Wu conv |
// [320,1344) x conv | [1344,2368) vision conv | [2368,4416) WkT/WvT tiles
__global__ __launch_bounds__(256) void prep_kernel(
        const float* __restrict__ Wu, const float* __restrict__ Wk,
        const float* __restrict__ Wv, const float* __restrict__ x,
        const float* __restrict__ vision, const float* __restrict__ bu,
        const unsigned* __restrict__ mask) {
    __shared__ float sh[32][33];
    int blk = blockIdx.x, tid = threadIdx.x;
    if (blk < 32) {                              // mask format detection
        int f = 0;
        for (int i = blk * 256 + tid; i < 32768; i += 32 * 256) {
            unsigned w = mask[i];
            if (w > 1u)           f |= 1;
            if (w == 0x3F800000u) f |= 2;
            if (w == 0x3F803F80u) f |= 4;
            if (w == 0x00003F80u) f |= 8;
        }
        if (f) atomicOr(&g_flags, f);
        return;
    }
    blk -= 32;
    if (blk < 32) {                              // rvec = bu@Wk, bo = bu@Wv
        const float* W = (blk < 16) ? Wk : Wv;
        int jbase = (blk & 15) * 64;
        int jl = tid & 63, isl = tid >> 6;
        int j = jbase + jl;
        float s = 0.f;
        int i0 = isl * 256;
        #pragma unroll 8
        for (int i = 0; i < 256; i++) {
            int ii = i0 + i;
            s += bu[ii] * W[(size_t)ii * ND + j];
        }
        ((float*)sh)[tid] = s;
        __syncthreads();
        if (isl == 0) {
            float* r = (float*)sh;
            float tot = r[jl] + r[64 + jl] + r[128 + jl] + r[192 + jl];
            if (blk < 16) g_rvec[j] = tot; else g_bo[j] = tot;
        }
        return;
    }
    blk -= 32;
    if (blk < 256) {                             // Wu -> bf16
        int q = blk * 256 + tid;
        st_bf16x4(&g_Wu16[q * 4], ((const float4*)Wu)[q]);
        return;
    }
    blk -= 256;
    if (blk < 1024) {                            // x -> bf16
        int q = blk * 256 + tid;
        st_bf16x4(&g_x16[q * 4], ((const float4*)x)[q]);
        return;
    }
    blk -= 1024;
    if (blk < 1024) {                            // vision -> bf16
        int q = blk * 256 + tid;
        st_bf16x4(&g_vis16[q * 4], ((const float4*)vision)[q]);
        return;
    }
    blk -= 1024;
    {                                            // transpose-convert Wk / Wv
        int mat = blk >> 10;                     // 0 = Wk, 1 = Wv
        int tt = blk & 1023;
        int Tr = (tt >> 5) * 32, Tc = (tt & 31) * 32;
        const float* M = mat ? Wv : Wk;
        __nv_bfloat16* O = mat ? g_WvT16 : g_WkT16;
        int r = tid >> 5, c = tid & 31;
        #pragma unroll
        for (int i = 0; i < 4; i++)
            sh[r + 8 * i][c] = M[(size_t)(Tr + r + 8 * i) * ND + Tc + c];
        __syncthreads();
        int ci = tid >> 3, rp = (tid & 7) * 2;
        #pragma unroll
        for (int j = 0; j < 2; j++) {
            int ri = rp + 16 * j;
            __nv_bfloat162 p = __floats2bfloat162_rn(sh[ri][ci], sh[ri + 1][ci]);
            *(unsigned*)&O[(size_t)(Tc + ci) * ND + Tr + ri] = *(unsigned*)&p;
        }
    }
}

// ---------------- index extraction: one warp per (b,t) ----------------
__global__ void extract_idx_kernel(const void* __restrict__ mraw) {
    int bt = blockIdx.x;
    int b = bt / NT, t = bt % NT;
    int lane = threadIdx.x;
    int flags = g_flags;
    int fmt = (flags & (4 | 8)) ? 3 : (flags & 2) ? 2 : (flags & 1) ? 1 : 0;
    int cnt = 0;
    const size_t base = (size_t)b * NV * NT + t;
    for (int c = 0; c < NV / 32; c++) {
        int v = c * 32 + lane;
        size_t e = base + (size_t)v * NT;
        bool on;
        if (fmt == 0)      on = ((const int*)mraw)[e] != 0;
        else if (fmt == 1) on = ((const unsigned char*)mraw)[e] != 0;
        else if (fmt == 2) on = ((const float*)mraw)[e] != 0.0f;
        else               on = ((const unsigned short*)mraw)[e] != 0;
        unsigned bal = __ballot_sync(0xFFFFFFFFu, on);
        if (on) {
            int pos = cnt + __popc(bal & ((1u << lane) - 1u));
            if (pos < NS) g_idx[bt * NS + pos] = v;
        }
        cnt += __popc(bal);
    }
    if (cnt > NS) cnt = NS;
    for (int s = cnt + lane; s < NS; s += 32) g_idx[bt * NS + s] = NV;
}

// ---------------- bf16 3-stage pipelined tensor GEMM (all TRANSB) ----------
// B is (N x K) row-major k-contiguous. BM=64, BK=32, 256 thr = 8 warps (2x4).
// MODE 0: z 0..3 -> B = (z<2 ? B0 : B1), K-half = z&1, C += z*csz
// MODE 1: z = K-half; C += z*csz
// MODE 2: EPI: C = acc + wrow[r]*bocol[c] + Xadd[r*ldc+c]
template <int BN, int MODE>
__global__ __launch_bounds__(256) void bgemm_kernel(
        const __nv_bfloat16* __restrict__ A,
        const __nv_bfloat16* __restrict__ B0,
        const __nv_bfloat16* __restrict__ B1,
        float* __restrict__ C,
        int kiter, int lda, int ldb, int ldc, int csz,
        const float* __restrict__ wrow,
        const float* __restrict__ bocol,
        const float* __restrict__ Xadd) {
    constexpr int BM = 64, BK = 32, STR = 40;   // word-stride 20 -> conflict-free
    constexpr int WN = BN / 4, NI = WN / 8;
    __shared__ __nv_bfloat16 smA[3][BM * STR];
    __shared__ __nv_bfloat16 smB[3][BN * STR];

    const __nv_bfloat16* Ap = A;
    const __nv_bfloat16* Bp = B0;
    float* Cp = C;
    if (MODE == 0) {
        int zz = blockIdx.z;
        Bp = (zz < 2) ? B0 : B1;
        int kb = (zz & 1) * (kiter * BK);
        Ap = A + kb; Bp += kb;
        Cp = C + (size_t)zz * csz;
    } else if (MODE == 1) {
        int zz = blockIdx.z;
        int kb = zz * (kiter * BK);
        Ap = A + kb; Bp = B0 + kb;
        Cp = C + (size_t)zz * csz;
    }

    int row0 = blockIdx.y * BM, col0 = blockIdx.x * BN;
    int tid = threadIdx.x;
    int warp = tid >> 5, lane = tid & 31;
    int wm = warp >> 2, wn = warp & 3;
    int g = lane >> 2, tg = lane & 3;

    float acc[2][NI][4] = {};

    auto load_stage = [&](int s, int k0) {
        {
            int m = tid >> 2, kq = tid & 3;      // 64 rows x 4 x cp16
            cp16(&smA[s][m * STR + kq * 8],
                 &Ap[(size_t)(row0 + m) * lda + k0 + kq * 8]);
        }
        if (BN == 64 || tid < 128) {
            int n = tid >> 2, kq = tid & 3;
            cp16(&smB[s][n * STR + kq * 8],
                 &Bp[(size_t)(col0 + n) * ldb + k0 + kq * 8]);
        }
        cp_commit();
    };

    load_stage(0, 0);
    load_stage(1, BK);

    for (int it = 0; it < kiter; it++) {
        cp_wait1();
        __syncthreads();
        if (it + 2 < kiter) load_stage((it + 2) % 3, (it + 2) * BK);
        else                cp_commit();

        const __nv_bfloat16* As_ = smA[it % 3];
        const __nv_bfloat16* Bs_ = smB[it % 3];
        #pragma unroll
        for (int ks = 0; ks < BK; ks += 16) {
            unsigned a[2][4];
            #pragma unroll
            for (int mi = 0; mi < 2; mi++) {
                int r = wm * 32 + mi * 16;
                a[mi][0] = *(const unsigned*)&As_[(r + g) * STR + ks + 2 * tg];
                a[mi][1] = *(const unsigned*)&As_[(r + 8 + g) * STR + ks + 2 * tg];
                a[mi][2] = *(const unsigned*)&As_[(r + g) * STR + ks + 8 + 2 * tg];
                a[mi][3] = *(const unsigned*)&As_[(r + 8 + g) * STR + ks + 8 + 2 * tg];
            }
            unsigned b[NI][2];
            #pragma unroll
            for (int ni = 0; ni < NI; ni++) {
                int c = wn * WN + ni * 8 + g;
                b[ni][0] = *(const unsigned*)&Bs_[c * STR + ks + 2 * tg];
                b[ni][1] = *(const unsigned*)&Bs_[c * STR + ks + 8 + 2 * tg];
            }
            #pragma unroll
            for (int mi = 0; mi < 2; mi++)
                #pragma unroll
                for (int ni = 0; ni < NI; ni++)
                    mma_bf16(acc[mi][ni], a[mi], b[ni]);
        }
        __syncthreads();
    }

    #pragma unroll
    for (int mi = 0; mi < 2; mi++) {
        #pragma unroll
        for (int ni = 0; ni < NI; ni++) {
            int r = row0 + wm * 32 + mi * 16 + g;
            int c = col0 + wn * WN + ni * 8 + tg * 2;
            float* a4 = acc[mi][ni];
            #pragma unroll
            for (int h = 0; h < 2; h++) {
                int rr = r + h * 8;
                float v0 = a4[h * 2], v1 = a4[h * 2 + 1];
                if (MODE == 2) {
                    float wr = wrow[rr];
                    v0 += wr * bocol[c]     + Xadd[(size_t)rr * ldc + c];
                    v1 += wr * bocol[c + 1] + Xadd[(size_t)rr * ldc + c + 1];
                }
                Cp[(size_t)rr * ldc + c]     = v0;
                Cp[(size_t)rr * ldc + c + 1] = v1;
            }
        }
    }
}

// ------- reduce split-K halves: P1 (bf16, as-is) + P2^T (bf16, transposed) ---
__global__ __launch_bounds__(256) void reduceP_kernel() {
    __shared__ float sh[32][33];
    int blk = blockIdx.x, tid = threadIdx.x;
    if (blk < 256) {                             // P1 = h0 + h1 -> bf16
        int q = blk * 256 + tid;
        const float4* h0 = (const float4*)g_Ph[0];
        const float4* h1 = (const float4*)g_Ph[1];
        float4 a = h0[q], b = h1[q];
        st_bf16x4(&g_P1_16[q * 4],
                  make_float4(a.x + b.x, a.y + b.y, a.z + b.z, a.w + b.w));
        return;
    }
    blk -= 256;                                  // P2^T tiles: 8 x 32
    int Tr = (blk >> 5) * 32, Tc = (blk & 31) * 32;
    int r = tid >> 5, c = tid & 31;
    #pragma unroll
    for (int i = 0; i < 4; i++) {
        size_t e = (size_t)(Tr + r + 8 * i) * ND + Tc + c;
        sh[r + 8 * i][c] = g_Ph[2][e] + g_Ph[3][e];
    }
    __syncthreads();
    int ci = tid >> 3, rp = (tid & 7) * 2;
    #pragma unroll
    for (int j = 0; j < 2; j++) {
        int ri = rp + 16 * j;
        __nv_bfloat162 p = __floats2bfloat162_rn(sh[ri][ci], sh[ri + 1][ci]);
        *(unsigned*)&g_P2T16[(size_t)(Tc + ci) * NCV + Tr + ri] = *(unsigned*)&p;
    }
}

// ---------------- qk: gather-dot (bf16 vision) + softmax stats ----------------
__global__ void qk_kernel(const float* __restrict__ x) {
    int bt = blockIdx.x, b = bt / NT;
    __shared__ float zs[NCV];
    __shared__ float red[256];
    __shared__ float qks[NS];
    int tid = threadIdx.x;
    zs[tid] = g_Zh[0][bt * NCV + tid] + g_Zh[1][bt * NCV + tid];
    const float* xr = x + (size_t)bt * ND;
    float p = 0.f;
    #pragma unroll
    for (int i = tid; i < ND; i += 256) p += g_rvec[i] * xr[i];
    red[tid] = p;
    __syncthreads();
    for (int o = 128; o > 0; o >>= 1) {
        if (tid < o) red[tid] += red[tid + o];
        __syncthreads();
    }
    float c0 = red[0];

    int w = tid >> 5, lane = tid & 31;
    const __nv_bfloat16* vb = g_vis16 + (size_t)b * NV * NCV;
    #pragma unroll
    for (int q = 0; q < 8; q++) {
        int s = w * 8 + q;
        int vidx = g_idx[bt * NS + s];
        float d = 0.f;
        if (vidx < NV) {
            const __nv_bfloat16* vr = vb + (size_t)vidx * NCV;
            #pragma unroll
            for (int i = 0; i < 4; i++) {
                int e = 2 * lane + 64 * i;
                __nv_bfloat162 pv = *(const __nv_bfloat162*)&vr[e];
                d += __bfloat162float(pv.x) * zs[e]
                   + __bfloat162float(pv.y) * zs[e + 1];
            }
        }
        for (int o = 16; o > 0; o >>= 1) d += __shfl_down_sync(0xFFFFFFFFu, d, o);
        if (lane == 0) {
            float qk = (vidx < NV) ? (d + c0) * (1.f / 32.f) - 100.f
                                   : c0 * (1.f / 32.f);
            qks[s] = qk;
            g_qk[bt * NS + s] = qk;
        }
    }
    __syncthreads();
    if (w == 0) {
        float q1 = qks[lane], q2 = qks[lane + 32];
        float mx = fmaxf(q1, q2);
        for (int o = 16; o > 0; o >>= 1)
            mx = fmaxf(mx, __shfl_xor_sync(0xFFFFFFFFu, mx, o));
        float l = expf(q1 - mx) + expf(q2 - mx);
        for (int o = 16; o > 0; o >>= 1) l += __shfl_xor_sync(0xFFFFFFFFu, l, o);
        if (lane == 0) { g_m[bt] = mx; g_l[bt] = l; }
    }
}

// ------- G16 = sum_s p_s * vision16[idx_s] (batch softmax merge fused) -------
__global__ void gather_g_kernel() {
    int bt = blockIdx.x, b = bt / NT;
    __shared__ float ps[NS];
    __shared__ float red[256];
    int tid = threadIdx.x;

    float m = g_m[b * NT + tid];
    red[tid] = m;
    __syncthreads();
    for (int o = 128; o > 0; o >>= 1) {
        if (tid < o) red[tid] = fmaxf(red[tid], red[tid + o]);
        __syncthreads();
    }
    float M = red[0];
    __syncthreads();
    red[tid] = g_l[b * NT + tid] * expf(m - M);
    __syncthreads();
    for (int o = 128; o > 0; o >>= 1) {
        if (tid < o) red[tid] += red[tid + o];
        __syncthreads();
    }
    float invL = 1.f / red[0];

    if (tid < NS) ps[tid] = expf(g_qk[bt * NS + tid] - M) * invL;
    __syncthreads();
    if (tid == 0) {
        float s = 0.f;
        #pragma unroll
        for (int i = 0; i < NS; i++) s += ps[i];
        g_w[bt] = s;
    }
    float acc = 0.f;
    const __nv_bfloat16* vb = g_vis16 + (size_t)b * NV * NCV;
    const int* ids = &g_idx[bt * NS];
    #pragma unroll 4
    for (int s = 0; s < NS; s++) {
        int vi = ids[s];
        if (vi < NV) acc += ps[s] * __bfloat162float(vb[(size_t)vi * NCV + tid]);
    }
    g_G16[bt * NCV + tid] = __float2bfloat16(acc);
}

// ---------------- launch ----------------
extern "C" void kernel_launch(void* const* d_in, const int* in_sizes, int n_in,
                              void* d_out, int out_size) {
    const float* x      = (const float*)d_in[0];
    const float* vision = (const float*)d_in[1];
    const void*  mask   = d_in[2];
    const float* Wu     = (const float*)d_in[3];
    const float* bu     = (const float*)d_in[4];
    const float* Wk     = (const float*)d_in[5];
    const float* Wv     = (const float*)d_in[6];
    float* out = (float*)d_out;

    float *Ph, *Zh;
    cudaGetSymbolAddress((void**)&Ph, g_Ph);
    cudaGetSymbolAddress((void**)&Zh, g_Zh);
    __nv_bfloat16 *Wu16, *WkT16, *WvT16, *x16, *P1_16, *P2T16, *G16;
    cudaGetSymbolAddress((void**)&Wu16, g_Wu16);
    cudaGetSymbolAddress((void**)&WkT16, g_WkT16);
    cudaGetSymbolAddress((void**)&WvT16, g_WvT16);
    cudaGetSymbolAddress((void**)&x16, g_x16);
    cudaGetSymbolAddress((void**)&P1_16, g_P1_16);
    cudaGetSymbolAddress((void**)&P2T16, g_P2T16);
    cudaGetSymbolAddress((void**)&G16, g_G16);
    float *bo, *w;
    cudaGetSymbolAddress((void**)&bo, g_bo);
    cudaGetSymbolAddress((void**)&w, g_w);

    // 1) fused prep: detect + rbo + conversions + W transposes
    prep_kernel<<<4416, 256>>>(Wu, Wk, Wv, x, vision, bu, (const unsigned*)mask);
    // 2) selected-index lists
    extract_idx_kernel<<<NBT, 32>>>(mask);
    // 3) P halves: z -> {P1,P2} x {K-half}; K=512 each
    bgemm_kernel<64, 0><<<dim3(ND / 64, NCV / 64, 4), 256>>>(
        Wu16, WkT16, WvT16, Ph, 512 / 32, ND, ND, ND, NCV * ND,
        nullptr, nullptr, nullptr);
    // 4) reduce halves -> P1 bf16, P2^T bf16
    reduceP_kernel<<<512, 256>>>();
    // 5) Z halves: Z = X @ P1^T, split-K=2, BN=32
    bgemm_kernel<32, 1><<<dim3(NCV / 32, NBT / 64, 2), 256>>>(
        x16, P1_16, nullptr, Zh, 512 / 32, ND, ND, NCV, NBT * NCV,
        nullptr, nullptr, nullptr);
    // 6) qk + per-token softmax stats
    qk_kernel<<<NBT, 256>>>(x);
    // 7) weighted gather G (batch softmax merge fused)
    gather_g_kernel<<<NBT, 256>>>();
    // 8) out = G @ P2 + w*bo + x
    bgemm_kernel<64, 2><<<dim3(ND / 64, NBT / 64, 1), 256>>>(
        G16, P2T16, nullptr, out, NCV / 32, NCV, NCV, ND, 0, w, bo, x);
}